// round 2
// baseline (speedup 1.0000x reference)
#include <cuda_runtime.h>
#include <math.h>

#define N 96
#define NN (N*N)            // 9216
#define LATENT 256
#define OUT_DIM 4656
#define ITERS 50
#define NBLK_E 96
#define CHUNK 36            // 9216 / 256

// ---------------- static device scratch (no allocations allowed) ----------------
__device__ float g_part_mu[256 * LATENT];
__device__ float g_part_ls[256 * LATENT];
__device__ float g_hidden[LATENT];
__device__ float g_kl;
__device__ float g_out[OUT_DIM];
__device__ float g_bce[64];
__device__ float g_A[NN];        // A'[i*N+j]
__device__ float g_Bm[NN];       // B'[a*N+b]
__device__ float g_SdT[NN];      // Sd transposed: [a*N+i]
__device__ float g_u[2][NN];     // x transposed: u[b*N + j] = x[j][b]
__device__ float g_sumsq[ITERS + 1];
__device__ unsigned int g_bar_count;
__device__ volatile unsigned int g_bar_release;

__device__ __forceinline__ int trioff(int i) { return i * (193 - i) / 2; }

// ---------------- Kernel A: split-K encoder matvec partials ----------------
__global__ void kA(const float* __restrict__ h,
                   const float* __restrict__ We11,
                   const float* __restrict__ We12) {
    __shared__ float sh[CHUNK];
    int b = blockIdx.x, t = threadIdx.x;
    if (t < CHUNK) sh[t] = h[b * CHUNK + t];
    __syncthreads();
    float smu = 0.f, sls = 0.f;
    long base = (long)b * CHUNK * LATENT + t;
#pragma unroll 4
    for (int k = 0; k < CHUNK; k++) {
        float hv = sh[k];
        smu = fmaf(hv, We11[base + (long)k * LATENT], smu);
        sls = fmaf(hv, We12[base + (long)k * LATENT], sls);
    }
    g_part_mu[b * LATENT + t] = smu;
    g_part_ls[b * LATENT + t] = sls;
}

// ---------------- Kernel B: reduce, reparam, KL, hidden layer ----------------
__global__ void kB(const float* __restrict__ eps,
                   const float* __restrict__ be11,
                   const float* __restrict__ be12,
                   const float* __restrict__ Wd1,
                   const float* __restrict__ bd1) {
    int t = threadIdx.x;
    float mu = be11[t], ls = be12[t];
    for (int b = 0; b < 256; b++) {
        mu += g_part_mu[b * LATENT + t];
        ls += g_part_ls[b * LATENT + t];
    }
    float z = fmaf(eps[t], expf(0.5f * ls), mu);
    float klp = 1.0f + ls - mu * mu - expf(ls);

    __shared__ float sz[LATENT];
    __shared__ float sred[8];
    sz[t] = z;
#pragma unroll
    for (int off = 16; off; off >>= 1) klp += __shfl_xor_sync(0xffffffffu, klp, off);
    if ((t & 31) == 0) sred[t >> 5] = klp;
    __syncthreads();
    if (t == 0) {
        float s = 0.f;
#pragma unroll
        for (int w = 0; w < 8; w++) s += sred[w];
        g_kl = -0.5f * s / (float)NN;
    }
    float acc = bd1[t];
#pragma unroll 8
    for (int l = 0; l < LATENT; l++) acc = fmaf(sz[l], Wd1[l * LATENT + t], acc);
    g_hidden[t] = fmaxf(acc, 0.f);
}

// ---------------- Kernel C: output layer, sigmoid, BCE partials ----------------
__global__ void kC(const float* __restrict__ Wd2,
                   const float* __restrict__ bd2,
                   const float* __restrict__ adj) {
    __shared__ float sH[LATENT];
    __shared__ float sred[4];
    int t = threadIdx.x;
    sH[t] = g_hidden[t];
    sH[t + 128] = g_hidden[t + 128];
    __syncthreads();
    int o = blockIdx.x * 128 + t;
    float term = 0.f;
    if (o < OUT_DIM) {
        float y = bd2[o];
#pragma unroll 8
        for (int l = 0; l < LATENT; l++) y = fmaf(sH[l], Wd2[l * OUT_DIM + o], y);
        float ov = 1.f / (1.f + expf(-y));
        g_out[o] = ov;
        // invert triu index: o -> (i,j), i<=j
        int i = (int)((193.0f - sqrtf(37249.0f - 8.0f * (float)o)) * 0.5f);
        if (i < 0) i = 0;
        if (i > 95) i = 95;
        while (i < 95 && trioff(i + 1) <= o) i++;
        while (i > 0 && trioff(i) > o) i--;
        int j = o - trioff(i) + i;
        // NOTE reference: _bce(inp=adj_vec, tgt=out) -> logs of adj entries
        float inp = adj[i * N + j];
        float li = fmaxf(logf(inp), -100.f);
        float l1 = fmaxf(log1pf(-inp), -100.f);
        term = fmaf(ov, li, (1.f - ov) * l1);
    }
#pragma unroll
    for (int off = 16; off; off >>= 1) term += __shfl_xor_sync(0xffffffffu, term, off);
    if ((t & 31) == 0) sred[t >> 5] = term;
    __syncthreads();
    if (t == 0) g_bce[blockIdx.x] = sred[0] + sred[1] + sred[2] + sred[3];
}

// ---------------- Kernel D: build A', B', Sd, init MPM state, finalize loss ----
__global__ void kD(const float* __restrict__ adj, float* __restrict__ d_out,
                   int write_loss) {
    __shared__ float sd[N], sdr[N], sfe[N], sfr[N];
    int t = threadIdx.x;
    if (t < N) {
        float s = 0.f;
        for (int j = 0; j < N; j++) s += adj[t * N + j];
        sfe[t] = s;
        sd[t] = adj[t * N + t];
        sdr[t] = g_out[trioff(t)];
        float sr = 0.f;
        for (int b = 0; b < N; b++) {
            int lo = min(t, b), hi = max(t, b);
            sr += g_out[trioff(lo) + hi - lo];
        }
        sfr[t] = sr;
    }
    __syncthreads();
    for (int idx = t; idx < NN; idx += blockDim.x) {
        int i = idx / N, j = idx - i * N;
        g_A[idx] = (i != j) ? adj[idx] * sd[i] * sd[j] : 0.f;
        int lo = min(i, j), hi = max(i, j);
        float rec = g_out[trioff(lo) + hi - lo];
        g_Bm[idx] = (i != j) ? rec * sdr[i] * sdr[j] : 0.f;
        // idx = a*N + i2
        int a = i, i2 = j;
        g_SdT[idx] = sd[i2] * sdr[a] / (fabsf(sfe[i2] - sfr[a]) + 1.0f);
        g_u[0][idx] = 1.0f / 96.0f;
    }
    if (t >= 1 && t <= ITERS) g_sumsq[t] = 0.f;
    if (t == 0) {
        g_sumsq[0] = 1.0f;   // ||x0||^2 = 9216 * (1/96)^2 = 1
        g_bar_count = 0u;
        g_bar_release = 0u;
        float s = 0.f;
        for (int b = 0; b < 37; b++) s += g_bce[b];
        if (write_loss) d_out[0] = -s / (float)OUT_DIM + g_kl;
    }
}

// ---------------- Kernel E: persistent MPM, 50 iterations ----------------
__global__ void __launch_bounds__(256) kE(float* __restrict__ d_out, int base) {
    __shared__ float sM[N];
    __shared__ float sred[8];
    int a = blockIdx.x, t = threadIdx.x;
    int lane = t & 31;
    bool active = (t < 192);
    int row = t >> 1;      // j in m-phase, i in update phase
    int half = t & 1;
    int b0 = half * 48;

    float rB[48], rA[48];
    float rSd = 0.f;
    if (active) {
#pragma unroll
        for (int q = 0; q < 48; q++) {
            rB[q] = g_Bm[a * N + b0 + q];
            rA[q] = g_A[row * N + b0 + q];
        }
        rSd = g_SdT[a * N + row];
    }

    for (int k = 0; k < ITERS; k++) {
        const float* ur = g_u[k & 1];
        float* uw = g_u[(k + 1) & 1];
        float rinv = rsqrtf(__ldcg(&g_sumsq[k]));

        // ---- M[j] = max_b B'[a,b] * x[j,b]  (x stored transposed: ur[b*N+j]) ----
        if (active) {
            float m0 = 0.f, m1 = 0.f, m2 = 0.f, m3 = 0.f;
#pragma unroll
            for (int q = 0; q < 48; q += 4) {
                int b = b0 + q;
                m0 = fmaxf(m0, rB[q]     * __ldcg(&ur[(b    ) * N + row]));
                m1 = fmaxf(m1, rB[q + 1] * __ldcg(&ur[(b + 1) * N + row]));
                m2 = fmaxf(m2, rB[q + 2] * __ldcg(&ur[(b + 2) * N + row]));
                m3 = fmaxf(m3, rB[q + 3] * __ldcg(&ur[(b + 3) * N + row]));
            }
            float m = fmaxf(fmaxf(m0, m1), fmaxf(m2, m3));
            m = fmaxf(m, __shfl_xor_sync(0xffffffffu, m, 1));
            if (!half) sM[row] = m;
        }
        __syncthreads();

        // ---- x_new[i,a] = rinv * (x[i,a]*Sd[i,a] + sum_j A'[i,j] M[j]) ----
        float sq = 0.f;
        if (active) {
            float a0 = 0.f, a1 = 0.f, a2 = 0.f, a3 = 0.f;
#pragma unroll
            for (int q = 0; q < 48; q += 4) {
                a0 = fmaf(rA[q],     sM[b0 + q],     a0);
                a1 = fmaf(rA[q + 1], sM[b0 + q + 1], a1);
                a2 = fmaf(rA[q + 2], sM[b0 + q + 2], a2);
                a3 = fmaf(rA[q + 3], sM[b0 + q + 3], a3);
            }
            float acc = (a0 + a1) + (a2 + a3);
            acc += __shfl_xor_sync(0xffffffffu, acc, 1);
            if (!half) {
                float v = rinv * fmaf(__ldcg(&ur[a * N + row]), rSd, acc);
                __stcg(&uw[a * N + row], v);
                sq = v * v;
            }
        }
#pragma unroll
        for (int off = 16; off; off >>= 1) sq += __shfl_xor_sync(0xffffffffu, sq, off);
        if (lane == 0) sred[t >> 5] = sq;
        __syncthreads();

        // ---- global barrier (96 blocks all co-resident on 152 SMs) ----
        if (t == 0) {
            float s = 0.f;
#pragma unroll
            for (int w = 0; w < 8; w++) s += sred[w];
            atomicAdd(&g_sumsq[k + 1], s);
            __threadfence();
            unsigned tgt = (unsigned)(k + 1) * (unsigned)NBLK_E;
            unsigned prev = atomicAdd(&g_bar_count, 1u);
            if (prev + 1u == tgt) {
                g_bar_release = (unsigned)(k + 1);
            } else {
                while (g_bar_release < (unsigned)(k + 1)) {}
                __threadfence();
            }
        }
        __syncthreads();
    }

    float rinvF = rsqrtf(__ldcg(&g_sumsq[ITERS]));
    const float* uf = g_u[ITERS & 1];   // ITERS even -> buffer 0
    if (t < N) {
        d_out[base + t * N + a] = __ldcg(&uf[a * N + t]) * rinvF;
    }
}

// ---------------- launch ----------------
extern "C" void kernel_launch(void* const* d_in, const int* in_sizes, int n_in,
                              void* d_out, int out_size) {
    const float* feats = (const float*)d_in[0];
    const float* adj   = (const float*)d_in[1];
    const float* eps   = (const float*)d_in[2];
    const float* We11  = (const float*)d_in[3];
    const float* be11  = (const float*)d_in[4];
    const float* We12  = (const float*)d_in[5];
    const float* be12  = (const float*)d_in[6];
    const float* Wd1   = (const float*)d_in[7];
    const float* bd1   = (const float*)d_in[8];
    const float* Wd2   = (const float*)d_in[9];
    const float* bd2   = (const float*)d_in[10];
    float* out = (float*)d_out;

    int has_loss = (out_size > NN) ? 1 : 0;   // [loss, assignment] vs [assignment]
    int base = has_loss ? 1 : 0;

    kA<<<256, 256>>>(feats, We11, We12);
    kB<<<1, 256>>>(eps, be11, be12, Wd1, bd1);
    kC<<<37, 128>>>(Wd2, bd2, adj);
    kD<<<1, 256>>>(adj, out, has_loss);
    kE<<<NBLK_E, 256>>>(out, base);
}